// round 1
// baseline (speedup 1.0000x reference)
#include <cuda_runtime.h>

// 4-qubit VQE energy. State indexed idx = q0*8 + q1*4 + q2*2 + q3.
// All circuit gates are real => psi stays real. One thread does everything.

__device__ __forceinline__ void apply1(float* psi, int w,
                                       float u00, float u01, float u10, float u11) {
    const int m = 8 >> w;
#pragma unroll
    for (int i = 0; i < 16; i++) {
        if (!(i & m)) {
            float a = psi[i], b = psi[i | m];
            psi[i]     = u00 * a + u01 * b;
            psi[i | m] = u10 * a + u11 * b;
        }
    }
}

__device__ __forceinline__ void cnot(float* psi, int c, int t) {
    const int mc = 8 >> c, mt = 8 >> t;
#pragma unroll
    for (int i = 0; i < 16; i++) {
        if ((i & mc) && !(i & mt)) {
            float tmp = psi[i];
            psi[i] = psi[i ^ mt];
            psi[i ^ mt] = tmp;
        }
    }
}

__device__ __forceinline__ void hgate(float* psi, int w) {
    const float r = 0.70710678118654752f;
    apply1(psi, w, r, r, r, -r);
}

// ry(theta): [[cos(t/2), -sin(t/2)], [sin(t/2), cos(t/2)]]
__device__ __forceinline__ void ry_p(float* psi, int w, float c, float s) {
    apply1(psi, w, c, -s, s, c);   // ry(+phi/8)
}
__device__ __forceinline__ void ry_m(float* psi, int w, float c, float s) {
    apply1(psi, w, c, s, -s, c);   // ry(-phi/8)
}

__global__ void vqe_energy_kernel(const float* __restrict__ phi_in,
                                  float* __restrict__ out) {
    float phi = phi_in[0];
    // ry(phi/8) half-angle = phi/16
    float t = phi * 0.0625f;
    float c, s;
    __sincosf(t, &s, &c);  // fast path; precision ~1e-7 here is plenty
    // Use accurate versions to be safe on tolerance:
    c = cosf(t);
    s = sinf(t);

    float psi[16];
#pragma unroll
    for (int i = 0; i < 16; i++) psi[i] = 0.0f;
    // |0000> then X0, X1  => |1100> = idx 12
    psi[12] = 1.0f;

    cnot(psi, 2, 3);
    cnot(psi, 0, 2);
    hgate(psi, 3);
    hgate(psi, 0);
    cnot(psi, 2, 3);
    cnot(psi, 0, 1);
    ry_p(psi, 1, c, s);
    ry_m(psi, 0, c, s);
    cnot(psi, 0, 3);
    hgate(psi, 3);
    cnot(psi, 3, 1);
    ry_p(psi, 1, c, s);
    ry_m(psi, 0, c, s);
    cnot(psi, 2, 1);
    cnot(psi, 2, 0);
    ry_m(psi, 1, c, s);
    ry_p(psi, 0, c, s);
    cnot(psi, 3, 1);
    hgate(psi, 3);
    cnot(psi, 0, 3);
    ry_m(psi, 1, c, s);
    ry_p(psi, 0, c, s);
    cnot(psi, 0, 1);
    cnot(psi, 2, 0);
    hgate(psi, 0);
    hgate(psi, 3);
    cnot(psi, 0, 2);
    cnot(psi, 2, 3);

    // Expectation values (all real arithmetic).
    float z0 = 0.f, z1 = 0.f, z2 = 0.f, z3 = 0.f;
    float zz02 = 0.f, zz13 = 0.f, zz03 = 0.f, zz12 = 0.f, zz01 = 0.f, zz23 = 0.f;
    float yyxx = 0.f, xxyy = 0.f, yxxy = 0.f, xyyx = 0.f;

#pragma unroll
    for (int i = 0; i < 16; i++) {
        int b0 = (i >> 3) & 1, b1 = (i >> 2) & 1, b2 = (i >> 1) & 1, b3 = i & 1;
        float p = psi[i] * psi[i];
        z0 += b0 ? -p : p;
        z1 += b1 ? -p : p;
        z2 += b2 ? -p : p;
        z3 += b3 ? -p : p;
        zz02 += (b0 ^ b2) ? -p : p;
        zz13 += (b1 ^ b3) ? -p : p;
        zz03 += (b0 ^ b3) ? -p : p;
        zz12 += (b1 ^ b2) ? -p : p;
        zz01 += (b0 ^ b1) ? -p : p;
        zz23 += (b2 ^ b3) ? -p : p;

        // Four-Pauli strings: (P psi)[i] = f(i) * psi[i^15],
        // f = -1 if the two Y-qubit bits are equal, else +1.
        float q = psi[i] * psi[i ^ 15];
        yyxx += (b0 == b1) ? -q : q;  // Y on 0,1
        xxyy += (b2 == b3) ? -q : q;  // Y on 2,3
        yxxy += (b0 == b3) ? -q : q;  // Y on 0,3
        xyyx += (b1 == b2) ? -q : q;  // Y on 1,2
    }

    float E = -0.042072551947440084f;
    E += -0.24274501260941383f * z2;
    E += -0.24274501260941383f * z3;
    E +=  0.1777135822909176f  * z0;
    E +=  0.1777135822909176f  * z1;
    E +=  0.12293330449299354f * zz02;
    E +=  0.12293330449299354f * zz13;
    E +=  0.1676833885560135f  * zz03;
    E +=  0.1676833885560135f  * zz12;
    E +=  0.17059759276836806f * zz01;
    E +=  0.17627661394181787f * zz23;
    E += -0.04475008406301996f * yyxx;
    E += -0.04475008406301996f * xxyy;
    E +=  0.04475008406301996f * yxxy;
    E +=  0.04475008406301996f * xyyx;

    out[0] = E;
}

extern "C" void kernel_launch(void* const* d_in, const int* in_sizes, int n_in,
                              void* d_out, int out_size) {
    const float* phi = (const float*)d_in[0];
    float* out = (float*)d_out;
    vqe_energy_kernel<<<1, 1>>>(phi, out);
}

// round 2
// speedup vs baseline: 1.3830x; 1.3830x over previous
#include <cuda_runtime.h>

// 4-qubit VQE energy, warp-parallel statevector: 16 amplitudes on 16 lanes
// (replicated across both warp halves so width-16 shuffles are uniform).
// idx = q0*8 + q1*4 + q2*2 + q3. All gates real => psi real.
//
// 1-qubit gates  : 1 shfl_xor + FMA
// commuting pairs: 3 concurrent shfls + 4-term FMA (one latency step)
// CNOT runs      : composed permutation, ONE shfl with per-lane src index

#define FULL 0xffffffffu
#define R_SQ2 0.70710678118654752f

// CNOT(c,t) as an index map: F(i) = i ^ ((i & mc) ? mt : 0)
__device__ __forceinline__ int Fcn(int i, int mc, int mt) {
    return i ^ ((i & mc) ? mt : 0);
}

__global__ void vqe_energy_kernel(const float* __restrict__ phi_in,
                                  float* __restrict__ out) {
    const int lane = threadIdx.x & 15;

    const float phi = phi_in[0];
    float s, c;
    __sincosf(phi * 0.0625f, &s, &c);   // half-angle of ry(phi/8)
    const float cc = c * c;

    // Per-lane observable weights (independent of psi -> off critical path)
    const float s0 = (lane & 8) ? -1.f : 1.f;
    const float s1 = (lane & 4) ? -1.f : 1.f;
    const float s2 = (lane & 2) ? -1.f : 1.f;
    const float s3 = (lane & 1) ? -1.f : 1.f;
    const float wp = 0.1777135822909176f  * (s0 + s1)
                   - 0.24274501260941383f * (s2 + s3)
                   + 0.12293330449299354f * (s0 * s2 + s1 * s3)
                   + 0.1676833885560135f  * (s0 * s3 + s1 * s2)
                   + 0.17059759276836806f * (s0 * s1)
                   + 0.17627661394181787f * (s2 * s3);
    const float wq = 0.04475008406301996f * ((s0 - s2) * (s1 - s3));

    // RY off-diagonal signs per lane (diag is always c)
    //  ry(+) on qubit w (mask m): o = (lane&m) ?  s : -s
    //  ry(-) on qubit w (mask m): o = (lane&m) ? -s :  s
    const float o1p = (lane & 4) ?  s : -s;   // ry+ on q1
    const float o1m = -o1p;                   // ry- on q1
    const float o0p = (lane & 8) ?  s : -s;   // ry+ on q0
    const float o0m = -o0p;                   // ry- on q0
    // H diagonal signs
    const float h3d = (lane & 1) ? -R_SQ2 : R_SQ2;
    const float h0d = (lane & 8) ? -R_SQ2 : R_SQ2;

    // initial state |1100> = index 12 (after X0, X1 folded in)
    float psi = (lane == 12) ? 1.0f : 0.0f;

    // --- 1: cnot(2,3); cnot(0,2)  [composed perm] ---
    {
        int src = Fcn(Fcn(lane, /*c0*/8, /*t2*/2), /*c2*/2, /*t3*/1);
        psi = __shfl_sync(FULL, psi, src, 16);
    }
    // --- 2: h(3); h(0)  [pair] ---
    {
        float pa = __shfl_xor_sync(FULL, psi, 1, 16);   // q3
        float pb = __shfl_xor_sync(FULL, psi, 8, 16);   // q0
        float pc = __shfl_xor_sync(FULL, psi, 9, 16);
        psi = (h3d * h0d) * psi + (h3d * R_SQ2) * pb + (R_SQ2 * h0d) * pa + 0.5f * pc;
    }
    // --- 3: cnot(2,3); cnot(0,1)  [disjoint, composed perm] ---
    {
        int src = Fcn(Fcn(lane, 8, 4), 2, 1);
        psi = __shfl_sync(FULL, psi, src, 16);
    }
    // --- 4: ry+(1); ry-(0)  [pair] ---
    {
        float pa = __shfl_xor_sync(FULL, psi, 4, 16);
        float pb = __shfl_xor_sync(FULL, psi, 8, 16);
        float pc = __shfl_xor_sync(FULL, psi, 12, 16);
        psi = cc * psi + (c * o0m) * pb + (o1p * c) * pa + (o1p * o0m) * pc;
    }
    // --- 5: cnot(0,3) ---
    psi = __shfl_sync(FULL, psi, Fcn(lane, 8, 1), 16);
    // --- 6: h(3) ---
    {
        float p = __shfl_xor_sync(FULL, psi, 1, 16);
        psi = h3d * psi + R_SQ2 * p;
    }
    // --- 7: cnot(3,1) ---
    psi = __shfl_sync(FULL, psi, Fcn(lane, 1, 4), 16);
    // --- 8: ry+(1); ry-(0)  [pair] ---
    {
        float pa = __shfl_xor_sync(FULL, psi, 4, 16);
        float pb = __shfl_xor_sync(FULL, psi, 8, 16);
        float pc = __shfl_xor_sync(FULL, psi, 12, 16);
        psi = cc * psi + (c * o0m) * pb + (o1p * c) * pa + (o1p * o0m) * pc;
    }
    // --- 9: cnot(2,1); cnot(2,0)  [composed perm] ---
    {
        int src = Fcn(Fcn(lane, 2, 8), 2, 4);
        psi = __shfl_sync(FULL, psi, src, 16);
    }
    // --- 10: ry-(1); ry+(0)  [pair] ---
    {
        float pa = __shfl_xor_sync(FULL, psi, 4, 16);
        float pb = __shfl_xor_sync(FULL, psi, 8, 16);
        float pc = __shfl_xor_sync(FULL, psi, 12, 16);
        psi = cc * psi + (c * o0p) * pb + (o1m * c) * pa + (o1m * o0p) * pc;
    }
    // --- 11: cnot(3,1) ---
    psi = __shfl_sync(FULL, psi, Fcn(lane, 1, 4), 16);
    // --- 12: h(3) ---
    {
        float p = __shfl_xor_sync(FULL, psi, 1, 16);
        psi = h3d * psi + R_SQ2 * p;
    }
    // --- 13: cnot(0,3) ---
    psi = __shfl_sync(FULL, psi, Fcn(lane, 8, 1), 16);
    // --- 14: ry-(1); ry+(0)  [pair] ---
    {
        float pa = __shfl_xor_sync(FULL, psi, 4, 16);
        float pb = __shfl_xor_sync(FULL, psi, 8, 16);
        float pc = __shfl_xor_sync(FULL, psi, 12, 16);
        psi = cc * psi + (c * o0p) * pb + (o1m * c) * pa + (o1m * o0p) * pc;
    }
    // --- 15: cnot(0,1); cnot(2,0)  [composed perm] ---
    {
        int src = Fcn(Fcn(lane, 2, 8), 8, 4);
        psi = __shfl_sync(FULL, psi, src, 16);
    }
    // --- 16: h(0); h(3)  [pair] ---
    {
        float pa = __shfl_xor_sync(FULL, psi, 1, 16);
        float pb = __shfl_xor_sync(FULL, psi, 8, 16);
        float pc = __shfl_xor_sync(FULL, psi, 9, 16);
        psi = (h3d * h0d) * psi + (h3d * R_SQ2) * pb + (R_SQ2 * h0d) * pa + 0.5f * pc;
    }
    // --- 17: cnot(0,2); cnot(2,3)  [composed perm] ---
    {
        int src = Fcn(Fcn(lane, 2, 1), 8, 2);
        psi = __shfl_sync(FULL, psi, src, 16);
    }

    // --- Energy: E_i = wp*psi^2 + wq*psi*psi[i^15] ---
    float p15 = __shfl_xor_sync(FULL, psi, 15, 16);
    float E = wp * psi * psi + wq * psi * p15;

    // butterfly reduce within the 16-lane group
    E += __shfl_xor_sync(FULL, E, 1, 16);
    E += __shfl_xor_sync(FULL, E, 2, 16);
    E += __shfl_xor_sync(FULL, E, 4, 16);
    E += __shfl_xor_sync(FULL, E, 8, 16);

    if (threadIdx.x == 0)
        out[0] = E + (-0.042072551947440084f);
}

extern "C" void kernel_launch(void* const* d_in, const int* in_sizes, int n_in,
                              void* d_out, int out_size) {
    const float* phi = (const float*)d_in[0];
    float* out = (float*)d_out;
    vqe_energy_kernel<<<1, 32>>>(phi, out);
}